// round 14
// baseline (speedup 1.0000x reference)
#include <cuda_runtime.h>
#include <cstdint>
#include <cstddef>

#define BB 16
#define AA 65536
#define TT 32
#define CC 21
#define NB1 2048
#define NB2 4096
#define CAP 262144
#define THR 256
#define SBC 1024              // shared survivor staging capacity
#define GRID_MAIN 592         // 4 blocks/SM * 148 SMs: one wave for kMain
#define GRID_IOU 512          // 1024 units / 2 per block; <= 592 conc: one wave
#define NU 1024               // total IoU work units (1024 anchors each)
#define UA 1024               // anchors per unit
#define NF4 (THR * CC / 4)    // 1344 float4 per chunk
#define CHUNK_BYTES (THR * CC * 4)   // 21504

struct State {
    unsigned long long packed[BB][TT];   // force-match argmax keys
    unsigned int forced[BB][AA / 32];    // forced-positive bitmask
    int numpos[BB], nneg[BB], kval[BB], blo[BB], cnt[BB];
    float possum[BB], bboxsum[BB], confl[BB], bboxl[BB];
    float plo[BB];                       // probability threshold (inverse focal)
    unsigned int h0[BB][NB1];            // sampled coarse histogram
};
__device__ State g;
__device__ float g_buf[BB][CAP];         // compacted candidate focal values
__device__ float g_maxiou[BB * AA];
__device__ unsigned char g_bestt[BB * AA];

// ---------------------------------------------------------------- helpers
__device__ __forceinline__ float focal_fn(float p, bool ispos) {
    float pt = ispos ? p : 1.0f - p;
    float af = ispos ? 0.25f : 0.75f;
    float om = 1.0f - pt;
    return -af * om * om * __logf(fmaxf(pt, 1e-6f));
}

__device__ __forceinline__ int focal_bin(float f) {
    return (int)((__float_as_uint(f) & 0x7FFFFFFFu) >> 20);
}

#define CP_ASYNC16(dst_u32, src_ptr) \
    asm volatile("cp.async.cg.shared.global [%0], [%1], 16;" \
                 :: "r"(dst_u32), "l"(src_ptr) : "memory")
#define CP_COMMIT() asm volatile("cp.async.commit_group;" ::: "memory")
#define CP_WAIT1() asm volatile("cp.async.wait_group 1;" ::: "memory")
#define CP_WAIT0() asm volatile("cp.async.wait_group 0;" ::: "memory")

// Block-wide (exactly 256 threads) descending bin selection over NB bins.
template <int NB, bool WS>
__device__ __forceinline__ void suffix_select(
    const unsigned* hc, const float* hs, long long k,
    unsigned* s_scnt, float* s_ssum,
    int* o_found, int* o_bin, long long* o_cum, float* o_sum)
{
    const int tid = threadIdx.x;          // requires blockDim.x == 256
    const int CH = NB / 256;
    unsigned myc = 0; float myf = 0.f;
#pragma unroll
    for (int j = 0; j < CH; j++) {
        myc += hc[tid * CH + j];
        if (WS) myf += hs[tid * CH + j];
    }
    s_scnt[tid] = myc;
    if (WS) s_ssum[tid] = myf;
    __syncthreads();
    for (int off = 1; off < 256; off <<= 1) {   // inclusive suffix scan
        unsigned vc = (tid + off < 256) ? s_scnt[tid + off] : 0u;
        float vf = 0.f;
        if (WS) vf = (tid + off < 256) ? s_ssum[tid + off] : 0.f;
        __syncthreads();
        s_scnt[tid] += vc;
        if (WS) s_ssum[tid] += vf;
        __syncthreads();
    }
    if (tid == 0) {
        *o_found = ((long long)s_scnt[0] >= k) ? 1 : 0;
        *o_bin = 0; *o_cum = 0; *o_sum = 0.f;
    }
    __syncthreads();
    if (*o_found) {
        long long S = (long long)s_scnt[tid];
        long long A = S - (long long)myc;
        if (A < k && S >= k) {                    // unique crossing chunk
            long long cum = A;
            float ab = WS ? (s_ssum[tid] - myf) : 0.f;
            int bin = tid * CH;
            for (int j = CH - 1; j >= 0; j--) {
                int bb = tid * CH + j;
                unsigned c = hc[bb];
                if (cum + (long long)c >= k) { bin = bb; break; }
                cum += c;
                if (WS) ab += hs[bb];
            }
            *o_bin = bin; *o_cum = cum; *o_sum = ab;
        }
    }
    __syncthreads();
}

// -------------------------------------------------------------- k0: zero
__global__ void kZero() {
    size_t n = sizeof(State) / 4;
    size_t i = (size_t)blockIdx.x * blockDim.x + threadIdx.x;
    if (i < n) ((unsigned int*)&g)[i] = 0u;
}

// --------------- k1: IoU — persistent one-wave, 4 anchors/thread,
// u32-hi precheck for the argmax keys, direct-global sampled histogram.
__global__ void __launch_bounds__(THR, 4)
kIoUSamp(const float* __restrict__ anchors, const float* __restrict__ tb,
         const float* __restrict__ conf) {
    int tid = threadIdx.x;
    __shared__ float4 stb4[TT];
    __shared__ float sarea[TT];
    __shared__ unsigned long long smax[TT];
    __shared__ int snp, snn;

#pragma unroll 1
    for (int u = blockIdx.x; u < NU; u += GRID_IOU) {
        int b = u >> 6;                        // 64 units per image
        int abase = (u & 63) * UA;             // image-local anchor base
        if (tid < TT) {
            float4 tv = ((const float4*)tb)[b * TT + tid];
            stb4[tid] = tv;
            sarea[tid] = (tv.z - tv.x) * (tv.w - tv.y);
            smax[tid] = 0ull;
        }
        if (tid == 0) { snp = 0; snn = 0; }
        __syncthreads();

        float4 av[4]; float ar[4]; float best[4]; int bt[4]; int aidx[4];
        size_t gb = (size_t)b * AA;
#pragma unroll
        for (int j = 0; j < 4; j++) {
            aidx[j] = abase + j * 256 + tid;
            av[j] = ((const float4*)anchors)[aidx[j]];
            ar[j] = (av[j].z - av[j].x) * (av[j].w - av[j].y);
            best[j] = -1.f; bt[j] = 0;
        }
#pragma unroll 8
        for (int t = 0; t < TT; t++) {
            float4 tv = stb4[t];
            float ta = sarea[t];
            unsigned hi = ((const unsigned*)smax)[2 * t + 1];  // monotone: stale-safe
#pragma unroll
            for (int j = 0; j < 4; j++) {
                float x1 = fmaxf(av[j].x, tv.x), y1 = fmaxf(av[j].y, tv.y);
                float x2 = fminf(av[j].z, tv.z), y2 = fminf(av[j].w, tv.w);
                float it = fmaxf(x2 - x1, 0.f) * fmaxf(y2 - y1, 0.f);
                float iou = __fdividef(it, ar[j] + ta - it + 1e-6f);
                if (iou > best[j]) { best[j] = iou; bt[j] = t; }  // first-index argmax
                unsigned bits = __float_as_uint(iou);             // iou >= 0: bit order ok
                if (bits >= hi) {              // rare slow path: exact 64-bit check
                    unsigned long long cand = ((unsigned long long)bits << 32) |
                        (unsigned long long)(0xFFFFFFFFu - (unsigned)aidx[j]);
                    unsigned long long cur = smax[t];
                    if (cand > cur) atomicMax(&smax[t], cand);
                }
            }
        }
        // epilogue: per-anchor results + counts
        int np = 0, nn = 0;
#pragma unroll
        for (int j = 0; j < 4; j++) {
            g_maxiou[gb + aidx[j]] = best[j];
            g_bestt[gb + aidx[j]] = (unsigned char)bt[j];
            np += (best[j] >= 0.5f);
            nn += (best[j] < 0.4f);
        }
        int pk = np | (nn << 8);               // fields can't overflow (<=128 each)
#pragma unroll
        for (int off = 16; off > 0; off >>= 1) pk += __shfl_down_sync(0xFFFFFFFFu, pk, off);
        if ((tid & 31) == 0) {
            atomicAdd(&snp, pk & 0xFF);
            atomicAdd(&snn, pk >> 8);
        }
        // sampled focal histogram: every 32nd anchor, straight to global
        if (tid < 32) {
            int sa = abase + tid * 32;
            const float* cp = conf + (gb + sa) * CC;
            float m = cp[0];
#pragma unroll
            for (int c = 1; c < CC; c++) m = fmaxf(m, cp[c]);
            float s = 0.f;
#pragma unroll
            for (int c = 0; c < CC; c++) s += __expf(cp[c] - m);
            float inv = __fdividef(1.0f, s);
#pragma unroll
            for (int c = 0; c < CC; c++) {
                float f = focal_fn(__expf(cp[c] - m) * inv, false);
                atomicAdd(&g.h0[b][focal_bin(f)], 1u);
            }
        }
        __syncthreads();                       // smax/snp final
        if (tid < TT) { unsigned long long v = smax[tid]; if (v) atomicMax(&g.packed[b][tid], v); }
        if (tid == 0) {
            if (snp) atomicAdd(&g.numpos[b], snp);
            if (snn) atomicAdd(&g.nneg[b], snn);
        }
        __syncthreads();                       // flush reads done before re-init
    }
}

// ------ k2: force-match, counts, blo/k, and probability threshold p_lo
__global__ void kPrep() {
    int b = blockIdx.x, tid = threadIdx.x;
    __shared__ unsigned int hc[NB1];
    __shared__ unsigned int scnt[256];
    __shared__ int s_found, s_bin;
    __shared__ long long s_cum;
    __shared__ float s_sum;
    if (tid < TT) {
        unsigned a = 0xFFFFFFFFu - (unsigned)(g.packed[b][tid] & 0xFFFFFFFFull);
        if (a < AA) {
            unsigned bit = 1u << (a & 31);
            unsigned old = atomicOr(&g.forced[b][a >> 5], bit);
            if (!(old & bit)) {
                float mi = g_maxiou[b * AA + a];
                if (mi < 0.5f) atomicAdd(&g.numpos[b], 1);
                if (mi < 0.4f) atomicAdd(&g.nneg[b], -1);
            }
        }
    }
    for (int i = tid; i < NB1; i += THR) hc[i] = g.h0[b][i];
    __syncthreads();
    long long np = g.numpos[b], nn = g.nneg[b];
    long long k = 3 * np; if (nn < k) k = nn;
    if (tid == 0) g.kval[b] = (int)k;
    if (k <= 0) { if (tid == 0) { g.blo[b] = NB1; g.plo[b] = 2.0f; } return; }
    long long target = k / 16 + 128;       // expected survivors ~ 2k + 4096
    suffix_select<NB1, false>(hc, nullptr, target, scnt, nullptr,
                              &s_found, &s_bin, &s_cum, &s_sum);
    if (tid == 0) {
        int blo = s_found ? s_bin : 0;
        g.blo[b] = blo;
        // invert focal at bin lower edge via FLOAT bisection
        float flo = __uint_as_float(((unsigned)blo) << 20);
        float plo = 0.f;
        if (flo > 0.f) {
            float lo = 0.f, hi = 1.f;
#pragma unroll
            for (int it = 0; it < 30; it++) {
                float p = 0.5f * (lo + hi);
                float pt = fmaxf(1.f - p, 1e-6f);
                float f = -0.75f * p * p * __logf(pt);
                if (f < flo) lo = p; else hi = p;
            }
            plo = lo * (1.f - 1e-3f);   // conservative margin: over-include
        }
        g.plo[b] = plo;
    }
}

// ------------------- k3: main pass, PERSISTENT + cp.async double-buffer.
__global__ void __launch_bounds__(THR, 4)
kMain(const float* __restrict__ conf, const float* __restrict__ bbox,
      const float* __restrict__ tb, const int* __restrict__ tl) {
    const int NCH = BB * AA / THR;            // 4096 chunks
    int tid = threadIdx.x;
    int lane = tid & 31;
    extern __shared__ char dynsmem[];
    float* buf0 = (float*)dynsmem;                         // 21504 B
    float* buf1 = (float*)(dynsmem + CHUNK_BYTES);         // 21504 B
    float* sbuf = (float*)(dynsmem + 2 * CHUNK_BYTES);     // SBC*4 B
    __shared__ float splo[BB];
    __shared__ int s_cnt, s_base;
    if (tid < BB) splo[tid] = g.plo[tid];
    if (tid == 0) s_cnt = 0;

    // issue cp.async for first chunk into buf0
    int chunk = blockIdx.x;
    {
        const float4* src = (const float4*)conf + (size_t)chunk * NF4;
        unsigned dst = (unsigned)__cvta_generic_to_shared(buf0);
#pragma unroll
        for (int kk = 0; kk < 5; kk++)
            CP_ASYNC16(dst + (tid + kk * 256) * 16, src + tid + kk * 256);
        if (tid < NF4 - 1280)
            CP_ASYNC16(dst + (tid + 1280) * 16, src + tid + 1280);
        CP_COMMIT();
    }

    int p = 0;
#pragma unroll 1
    for (; chunk < NCH; chunk += GRID_MAIN) {
        int b = chunk >> 8;
        int ga = chunk * THR + tid;            // flat anchor index (b*AA + a)
        float* cur = p ? buf1 : buf0;
        float* nxtbuf = p ? buf0 : buf1;
        int nxt = chunk + GRID_MAIN;
        if (nxt < NCH) {                       // issue prefetch of next chunk
            const float4* src = (const float4*)conf + (size_t)nxt * NF4;
            unsigned dst = (unsigned)__cvta_generic_to_shared(nxtbuf);
#pragma unroll
            for (int kk = 0; kk < 5; kk++)
                CP_ASYNC16(dst + (tid + kk * 256) * 16, src + tid + kk * 256);
            if (tid < NF4 - 1280)
                CP_ASYNC16(dst + (tid + 1280) * 16, src + tid + 1280);
            CP_COMMIT();
            CP_WAIT1();                        // current chunk's group done
        } else {
            CP_WAIT0();
        }
        float mi = g_maxiou[ga];
        unsigned fword = ((const unsigned*)g.forced)[ga >> 5];
        int bt = g_bestt[ga];
        __syncthreads();                       // (B) staged data visible to all

        bool forced = (fword >> (ga & 31)) & 1;
        bool pos = (mi >= 0.5f) || forced;
        bool neg = (mi < 0.4f) && !forced;
        float psC = 0.f, bbC = 0.f;
        if (pos || neg) {
            const float* row = cur + tid * CC; // stride-21: conflict-free
            float s = 0.f;
#pragma unroll
            for (int c = 0; c < CC; c++) s += __expf(row[c]);   // x~N(0,1): safe

            if (neg) {
                // logit-domain threshold; -1e-3 slack covers __logf ulp error
                float lthr = __logf(splo[b] * s) - 1e-3f;
                float inv = __fdividef(1.0f, s);
#pragma unroll
                for (int c = 0; c < CC; c++) {
                    if (row[c] >= lthr) {      // rare survivor -> shared staging
                        float f = focal_fn(__expf(row[c]) * inv, false);
                        int idx = atomicAdd(&s_cnt, 1);
                        if (idx < SBC) sbuf[idx] = f;
                        else {                 // overflow: direct global (rare)
                            int gi = atomicAdd(&g.cnt[b], 1);
                            if (gi < CAP) g_buf[b][gi] = f;
                        }
                    }
                }
            } else {
                int tc = tl[b * TT + bt];
                float inv = __fdividef(1.0f, s);
#pragma unroll
                for (int c = 0; c < CC; c++)
                    psC += focal_fn(__expf(row[c]) * inv, c == tc);

                float4 bp = ((const float4*)bbox)[(size_t)ga];
                float4 tv = ((const float4*)tb)[b * TT + bt];
                float t0 = tv.x, t1 = tv.y, t2 = tv.z, t3 = tv.w;
                float x1 = fmaxf(bp.x, t0), y1 = fmaxf(bp.y, t1);
                float x2 = fminf(bp.z, t2), y2 = fminf(bp.w, t3);
                float inter = fmaxf(x2 - x1, 0.f) * fmaxf(y2 - y1, 0.f);
                float a1 = (bp.z - bp.x) * (bp.w - bp.y);
                float a2 = (t2 - t0) * (t3 - t1);
                float uni = a1 + a2 - inter;
                float iou = inter / (uni + 1e-6f);
                float ex1 = fminf(bp.x, t0), ey1 = fminf(bp.y, t1);
                float ex2 = fmaxf(bp.z, t2), ey2 = fmaxf(bp.w, t3);
                float enc = (ex2 - ex1) * (ey2 - ey1);
                float gl = 1.f - (iou - (enc - uni) / (enc + 1e-6f));
                float l1 = 0.f, d, ad;
                d = bp.x - t0; ad = fabsf(d); l1 += (ad < 1.f) ? 0.5f * d * d : ad - 0.5f;
                d = bp.y - t1; ad = fabsf(d); l1 += (ad < 1.f) ? 0.5f * d * d : ad - 0.5f;
                d = bp.z - t2; ad = fabsf(d); l1 += (ad < 1.f) ? 0.5f * d * d : ad - 0.5f;
                d = bp.w - t3; ad = fabsf(d); l1 += (ad < 1.f) ? 0.5f * d * d : ad - 0.5f;
                l1 *= 0.25f;
                bbC = gl + 0.5f * l1;
            }
        }
        // per-chunk pos flush (fires only on the rare pos-containing chunks)
#pragma unroll
        for (int off = 16; off > 0; off >>= 1) {
            psC += __shfl_down_sync(0xFFFFFFFFu, psC, off);
            bbC += __shfl_down_sync(0xFFFFFFFFu, bbC, off);
        }
        if (lane == 0) {
            if (psC != 0.f) atomicAdd(&g.possum[b], psC);
            if (bbC != 0.f) atomicAdd(&g.bboxsum[b], bbC);
        }
        __syncthreads();                       // (C) survivors all staged
        int nf = s_cnt; if (nf > SBC) nf = SBC;
        if (tid == 0 && nf > 0) s_base = atomicAdd(&g.cnt[b], nf);
        __syncthreads();                       // (D) base visible
        if (nf > 0) {
            int base = s_base;
            for (int i = tid; i < nf; i += THR)
                if (base + i < CAP) g_buf[b][base + i] = sbuf[i];
        }
        if (tid == 0) s_cnt = 0;               // ordered by sync (B) next iter
        p ^= 1;
    }
}

// ------- k4: exact top-k (2-level radix) + INLINE exact fallback if the
// sampled threshold under-covered (uniform branch; never taken in practice).
__global__ void kSelect(const float* __restrict__ conf) {
    int b = blockIdx.x, tid = threadIdx.x;
    __shared__ unsigned int hc[NB2];
    __shared__ float hs[NB2];
    __shared__ unsigned int scnt[256];
    __shared__ float ssum[256];
    __shared__ int s_found, s_bin;
    __shared__ long long s_cum;
    __shared__ float s_sum;
    int n = g.cnt[b];
    long long k = g.kval[b];
    long long np = g.numpos[b];
    bool bad = (n > CAP);
    float topk = 0.f;
    if (k > 0 && !bad) {
        for (int i = tid; i < NB1; i += THR) { hc[i] = 0; hs[i] = 0.f; }
        __syncthreads();
        for (int i = tid; i < n; i += THR) {
            float v = g_buf[b][i];
            int bin = focal_bin(v);
            atomicAdd(&hc[bin], 1u);
            atomicAdd(&hs[bin], v);
        }
        __syncthreads();
        suffix_select<NB1, true>(hc, hs, k, scnt, ssum, &s_found, &s_bin, &s_cum, &s_sum);
        if (!s_found) {
            bad = true;                                 // under-coverage
        } else {
            int bstar = s_bin;
            long long rem = k - s_cum;
            float above = s_sum;
            unsigned cstar = hc[bstar];
            float sstar = hs[bstar];
            __syncthreads();
            if (rem >= (long long)cstar) {
                topk = above + sstar;
            } else {
                for (int i = tid; i < NB2; i += THR) { hc[i] = 0; hs[i] = 0.f; }
                __syncthreads();
                for (int i = tid; i < n; i += THR) {
                    float v = g_buf[b][i];
                    unsigned bits = __float_as_uint(v) & 0x7FFFFFFFu;
                    if ((int)(bits >> 20) == bstar) {
                        int sb = (bits >> 8) & 0xFFF;
                        atomicAdd(&hc[sb], 1u);
                        atomicAdd(&hs[sb], v);
                    }
                }
                __syncthreads();
                suffix_select<NB2, true>(hc, hs, rem, scnt, ssum, &s_found, &s_bin, &s_cum, &s_sum);
                long long rem2 = rem - s_cum;
                float part = 0.f;
                unsigned c2 = hc[s_bin];
                if (rem2 >= (long long)c2) part = hs[s_bin];
                else if (rem2 > 0 && c2 > 0) part = (float)rem2 * (hs[s_bin] / (float)c2);
                topk = above + s_sum + part;
            }
        }
    }
    if (bad && k > 0) {
        // exact fallback: full histogram over all negatives (uniform branch)
        __syncthreads();
        for (int i = tid; i < NB1; i += THR) { hc[i] = 0; hs[i] = 0.f; }
        __syncthreads();
        for (int ch = 0; ch < AA / THR; ch++) {
            int a = ch * THR + tid;
            float mi = g_maxiou[b * AA + a];
            bool forced = (g.forced[b][a >> 5] >> (a & 31)) & 1;
            if (mi < 0.4f && !forced) {
                const float* row = conf + ((size_t)b * AA + a) * CC;
                float m = row[0];
#pragma unroll
                for (int c = 1; c < CC; c++) m = fmaxf(m, row[c]);
                float s = 0.f;
#pragma unroll
                for (int c = 0; c < CC; c++) s += __expf(row[c] - m);
                float inv = __fdividef(1.0f, s);
#pragma unroll
                for (int c = 0; c < CC; c++) {
                    float f = focal_fn(__expf(row[c] - m) * inv, false);
                    int bin = focal_bin(f);
                    atomicAdd(&hc[bin], 1u);
                    atomicAdd(&hs[bin], f);
                }
            }
        }
        __syncthreads();
        suffix_select<NB1, true>(hc, hs, k, scnt, ssum, &s_found, &s_bin, &s_cum, &s_sum);
        float ab = s_sum;
        long long rem = k - s_cum;
        unsigned c = hc[s_bin];
        if (rem >= (long long)c) ab += hs[s_bin];
        else if (rem > 0 && c > 0) ab += (float)rem * (hs[s_bin] / (float)c);
        topk = ab;
    }
    if (tid == 0) {
        long long dn = np + k; if (dn < 1) dn = 1;
        g.confl[b] = (g.possum[b] + topk) / (float)dn;
        g.bboxl[b] = (np > 0) ? g.bboxsum[b] / (float)np : 0.f;
    }
}

// --------------------------------------------------------- k5: finalize
__global__ void kFinal(float* out) {
    if (threadIdx.x == 0) {
        float cs = 0.f, bs = 0.f;
        for (int b = 0; b < BB; b++) { cs += g.confl[b]; bs += g.bboxl[b]; }
        cs *= (1.0f / BB); bs *= (1.0f / BB);
        out[0] = cs + bs;
        out[1] = cs;
        out[2] = bs;
    }
}

// ---------------------------------------------------------------- launch
extern "C" void kernel_launch(void* const* d_in, const int* in_sizes, int n_in,
                              void* d_out, int out_size) {
    const float* conf = (const float*)d_in[0];
    const float* bbox = (const float*)d_in[1];
    const float* anch = (const float*)d_in[2];
    const float* tb = (const float*)d_in[3];
    const int* tl = (const int*)d_in[4];
    float* out = (float*)d_out;

    const int dynBytes = 2 * CHUNK_BYTES + SBC * 4;   // 47104
    cudaFuncSetAttribute((const void*)kMain,
                         cudaFuncAttributeMaxDynamicSharedMemorySize, dynBytes);
    cudaFuncSetAttribute((const void*)kMain,
                         cudaFuncAttributePreferredSharedMemoryCarveout, 100);

    int nz = (int)(sizeof(State) / 4);
    kZero<<<(nz + 255) / 256, 256>>>();
    kIoUSamp<<<GRID_IOU, THR>>>(anch, tb, conf);     // persistent, one wave
    kPrep<<<BB, THR>>>();
    kMain<<<GRID_MAIN, THR, dynBytes>>>(conf, bbox, tb, tl);   // persistent
    kSelect<<<BB, THR>>>(conf);        // 256 threads: suffix_select contract
    kFinal<<<1, 32>>>(out);
}

// round 15
// speedup vs baseline: 1.0700x; 1.0700x over previous
#include <cuda_runtime.h>
#include <cstdint>
#include <cstddef>

#define BB 16
#define AA 65536
#define TT 32
#define CC 21
#define NB1 2048
#define NB2 4096
#define CAP 262144
#define THR 256
#define SBC 1024              // shared survivor staging capacity
#define GRID_MAIN 592         // 4 blocks/SM * 148 SMs: one wave for kMain
#define NF4 (THR * CC / 4)    // 1344 float4 per chunk
#define CHUNK_BYTES (THR * CC * 4)   // 21504

struct State {
    unsigned long long packed[BB][TT];   // force-match argmax keys (MUST be first: kZero seeds it)
    unsigned int forced[BB][AA / 32];    // forced-positive bitmask
    int numpos[BB], nneg[BB], kval[BB], blo[BB], cnt[BB];
    float possum[BB], bboxsum[BB], confl[BB], bboxl[BB];
    float plo[BB];                       // probability threshold (inverse focal)
    unsigned int h0[BB][NB1];            // sampled coarse histogram
};
__device__ State g;
__device__ float g_buf[BB][CAP];         // compacted candidate focal values
__device__ float g_maxiou[BB * AA];
__device__ unsigned char g_bestt[BB * AA];

// ---------------------------------------------------------------- helpers
__device__ __forceinline__ float focal_fn(float p, bool ispos) {
    float pt = ispos ? p : 1.0f - p;
    float af = ispos ? 0.25f : 0.75f;
    float om = 1.0f - pt;
    return -af * om * om * __logf(fmaxf(pt, 1e-6f));
}

__device__ __forceinline__ int focal_bin(float f) {
    return (int)((__float_as_uint(f) & 0x7FFFFFFFu) >> 20);
}

#define CP_ASYNC16(dst_u32, src_ptr) \
    asm volatile("cp.async.cg.shared.global [%0], [%1], 16;" \
                 :: "r"(dst_u32), "l"(src_ptr) : "memory")
#define CP_COMMIT() asm volatile("cp.async.commit_group;" ::: "memory")
#define CP_WAIT1() asm volatile("cp.async.wait_group 1;" ::: "memory")
#define CP_WAIT0() asm volatile("cp.async.wait_group 0;" ::: "memory")

// Block-wide (exactly 256 threads) descending bin selection over NB bins.
template <int NB, bool WS>
__device__ __forceinline__ void suffix_select(
    const unsigned* hc, const float* hs, long long k,
    unsigned* s_scnt, float* s_ssum,
    int* o_found, int* o_bin, long long* o_cum, float* o_sum)
{
    const int tid = threadIdx.x;          // requires blockDim.x == 256
    const int CH = NB / 256;
    unsigned myc = 0; float myf = 0.f;
#pragma unroll
    for (int j = 0; j < CH; j++) {
        myc += hc[tid * CH + j];
        if (WS) myf += hs[tid * CH + j];
    }
    s_scnt[tid] = myc;
    if (WS) s_ssum[tid] = myf;
    __syncthreads();
    for (int off = 1; off < 256; off <<= 1) {   // inclusive suffix scan
        unsigned vc = (tid + off < 256) ? s_scnt[tid + off] : 0u;
        float vf = 0.f;
        if (WS) vf = (tid + off < 256) ? s_ssum[tid + off] : 0.f;
        __syncthreads();
        s_scnt[tid] += vc;
        if (WS) s_ssum[tid] += vf;
        __syncthreads();
    }
    if (tid == 0) {
        *o_found = ((long long)s_scnt[0] >= k) ? 1 : 0;
        *o_bin = 0; *o_cum = 0; *o_sum = 0.f;
    }
    __syncthreads();
    if (*o_found) {
        long long S = (long long)s_scnt[tid];
        long long A = S - (long long)myc;
        if (A < k && S >= k) {                    // unique crossing chunk
            long long cum = A;
            float ab = WS ? (s_ssum[tid] - myf) : 0.f;
            int bin = tid * CH;
            for (int j = CH - 1; j >= 0; j--) {
                int bb = tid * CH + j;
                unsigned c = hc[bb];
                if (cum + (long long)c >= k) { bin = bb; break; }
                cum += c;
                if (WS) ab += hs[bb];
            }
            *o_bin = bin; *o_cum = cum; *o_sum = ab;
        }
    }
    __syncthreads();
}

// -------------------- k0 (x3): zero state range; seed packed with
// (iou=0, anchor=0) keys = exact argmax result for all-zero IoU columns.
__global__ void kZeroRange(int off, int end) {
    int i = off + blockIdx.x * blockDim.x + threadIdx.x;
    if (i < end) {
        unsigned v = 0u;
        if (i < BB * TT * 2 && (i & 1) == 0) v = 0xFFFFFFFFu;  // low word of seed key
        ((unsigned int*)&g)[i] = v;
    }
}

// --------------- k1: IoU (2 anchors/thread) + zero-overlap skip (no div,
// no shared atomics for the 95% non-overlapping pairs), hoisted hi precheck.
__global__ void kIoUSamp(const float* __restrict__ anchors, const float* __restrict__ tb,
                         const float* __restrict__ conf) {
    int b = blockIdx.y;
    int tid = threadIdx.x;
    int a0 = blockIdx.x * (2 * THR);
    int a1 = a0 + tid, a2 = a0 + THR + tid;
    __shared__ float4 stb4[TT];
    __shared__ float sarea[TT];
    __shared__ unsigned long long smax[TT];
    __shared__ int snp, snn;
    __shared__ unsigned int sh[NB1];
    for (int i = tid; i < NB1; i += THR) sh[i] = 0;
    if (tid < TT) {
        float4 tv = ((const float4*)tb)[b * TT + tid];
        stb4[tid] = tv;
        sarea[tid] = (tv.z - tv.x) * (tv.w - tv.y);
        smax[tid] = 0ull;
    }
    if (tid == 0) { snp = 0; snn = 0; }
    __syncthreads();

    float4 av1 = ((const float4*)anchors)[a1];
    float4 av2 = ((const float4*)anchors)[a2];
    float arp1 = (av1.z - av1.x) * (av1.w - av1.y) + 1e-6f;
    float arp2 = (av2.z - av2.x) * (av2.w - av2.y) + 1e-6f;
    float best1 = 0.f, best2 = 0.f;        // all-zero row -> argmax = 0 (first index)
    int bt1 = 0, bt2 = 0;
    unsigned long long lo1 = (unsigned long long)(0xFFFFFFFFu - (unsigned)a1);
    unsigned long long lo2 = (unsigned long long)(0xFFFFFFFFu - (unsigned)a2);
#pragma unroll 8
    for (int t = 0; t < TT; t++) {
        float4 tv = stb4[t];
        float ta = sarea[t];
        unsigned hi = ((const unsigned*)smax)[2 * t + 1];   // monotone: stale-safe
        float dx1 = fminf(av1.z, tv.z) - fmaxf(av1.x, tv.x);
        float dy1 = fminf(av1.w, tv.w) - fmaxf(av1.y, tv.y);
        float dx2 = fminf(av2.z, tv.z) - fmaxf(av2.x, tv.x);
        float dy2 = fminf(av2.w, tv.w) - fmaxf(av2.y, tv.y);
        if (dx1 > 0.f && dy1 > 0.f) {       // overlapping pairs only (~5%)
            float it = dx1 * dy1;
            float iou = __fdividef(it, arp1 + ta - it);
            if (iou > best1) { best1 = iou; bt1 = t; }      // first-index argmax
            if (__float_as_uint(iou) >= hi) {               // rare exact path
                unsigned long long cand = ((unsigned long long)__float_as_uint(iou) << 32) | lo1;
                if (cand > smax[t]) atomicMax(&smax[t], cand);
            }
        }
        if (dx2 > 0.f && dy2 > 0.f) {
            float it = dx2 * dy2;
            float iou = __fdividef(it, arp2 + ta - it);
            if (iou > best2) { best2 = iou; bt2 = t; }
            if (__float_as_uint(iou) >= hi) {
                unsigned long long cand = ((unsigned long long)__float_as_uint(iou) << 32) | lo2;
                if (cand > smax[t]) atomicMax(&smax[t], cand);
            }
        }
    }
    g_maxiou[b * AA + a1] = best1;
    g_bestt[b * AA + a1] = (unsigned char)bt1;
    g_maxiou[b * AA + a2] = best2;
    g_bestt[b * AA + a2] = (unsigned char)bt2;

    unsigned pb1 = __ballot_sync(0xFFFFFFFFu, best1 >= 0.5f);
    unsigned nb1 = __ballot_sync(0xFFFFFFFFu, best1 < 0.4f);
    unsigned pb2 = __ballot_sync(0xFFFFFFFFu, best2 >= 0.5f);
    unsigned nb2 = __ballot_sync(0xFFFFFFFFu, best2 < 0.4f);
    if ((tid & 31) == 0) {
        atomicAdd(&snp, __popc(pb1) + __popc(pb2));
        atomicAdd(&snn, __popc(nb1) + __popc(nb2));
    }

    // fused 1/32-sampled focal histogram (16 sampled anchors per 512-block)
    if (tid < 16) {
        int sa = a0 + tid * 32;
        const float* cp = conf + ((size_t)b * AA + sa) * CC;
        float m = cp[0];
#pragma unroll
        for (int c = 1; c < CC; c++) m = fmaxf(m, cp[c]);
        float s = 0.f;
#pragma unroll
        for (int c = 0; c < CC; c++) s += __expf(cp[c] - m);
        float inv = __fdividef(1.0f, s);
#pragma unroll
        for (int c = 0; c < CC; c++) {
            float f = focal_fn(__expf(cp[c] - m) * inv, false);
            atomicAdd(&sh[focal_bin(f)], 1u);
        }
    }
    __syncthreads();
    if (tid < TT) { unsigned long long v = smax[tid]; if (v) atomicMax(&g.packed[b][tid], v); }
    if (tid == 0) { atomicAdd(&g.numpos[b], snp); atomicAdd(&g.nneg[b], snn); }
    for (int i = tid; i < NB1; i += THR)
        if (sh[i]) atomicAdd(&g.h0[b][i], sh[i]);
}

// ------ k2: force-match, counts, blo/k, and probability threshold p_lo
__global__ void kPrep() {
    int b = blockIdx.x, tid = threadIdx.x;
    __shared__ unsigned int hc[NB1];
    __shared__ unsigned int scnt[256];
    __shared__ int s_found, s_bin;
    __shared__ long long s_cum;
    __shared__ float s_sum;
    if (tid < TT) {
        unsigned a = 0xFFFFFFFFu - (unsigned)(g.packed[b][tid] & 0xFFFFFFFFull);
        if (a < AA) {
            unsigned bit = 1u << (a & 31);
            unsigned old = atomicOr(&g.forced[b][a >> 5], bit);
            if (!(old & bit)) {
                float mi = g_maxiou[b * AA + a];
                if (mi < 0.5f) atomicAdd(&g.numpos[b], 1);
                if (mi < 0.4f) atomicAdd(&g.nneg[b], -1);
            }
        }
    }
    for (int i = tid; i < NB1; i += THR) hc[i] = g.h0[b][i];
    __syncthreads();
    long long np = g.numpos[b], nn = g.nneg[b];
    long long k = 3 * np; if (nn < k) k = nn;
    if (tid == 0) g.kval[b] = (int)k;
    if (k <= 0) { if (tid == 0) { g.blo[b] = NB1; g.plo[b] = 2.0f; } return; }
    long long target = k / 16 + 128;       // expected survivors ~ 2k + 4096
    suffix_select<NB1, false>(hc, nullptr, target, scnt, nullptr,
                              &s_found, &s_bin, &s_cum, &s_sum);
    if (tid == 0) {
        int blo = s_found ? s_bin : 0;
        g.blo[b] = blo;
        // invert focal at bin lower edge via FLOAT bisection
        float flo = __uint_as_float(((unsigned)blo) << 20);
        float plo = 0.f;
        if (flo > 0.f) {
            float lo = 0.f, hi = 1.f;
#pragma unroll
            for (int it = 0; it < 30; it++) {
                float p = 0.5f * (lo + hi);
                float pt = fmaxf(1.f - p, 1e-6f);
                float f = -0.75f * p * p * __logf(pt);
                if (f < flo) lo = p; else hi = p;
            }
            plo = lo * (1.f - 1e-3f);   // conservative margin: over-include
        }
        g.plo[b] = plo;
    }
}

// ------------------- k3: main pass, PERSISTENT + cp.async double-buffer.
__global__ void __launch_bounds__(THR, 4)
kMain(const float* __restrict__ conf, const float* __restrict__ bbox,
      const float* __restrict__ tb, const int* __restrict__ tl) {
    const int NCH = BB * AA / THR;            // 4096 chunks
    int tid = threadIdx.x;
    int lane = tid & 31;
    extern __shared__ char dynsmem[];
    float* buf0 = (float*)dynsmem;                         // 21504 B
    float* buf1 = (float*)(dynsmem + CHUNK_BYTES);         // 21504 B
    float* sbuf = (float*)(dynsmem + 2 * CHUNK_BYTES);     // SBC*4 B
    __shared__ float splo[BB];
    __shared__ int s_cnt, s_base;
    if (tid < BB) splo[tid] = g.plo[tid];
    if (tid == 0) s_cnt = 0;

    // issue cp.async for first chunk into buf0
    int chunk = blockIdx.x;
    {
        const float4* src = (const float4*)conf + (size_t)chunk * NF4;
        unsigned dst = (unsigned)__cvta_generic_to_shared(buf0);
#pragma unroll
        for (int kk = 0; kk < 5; kk++)
            CP_ASYNC16(dst + (tid + kk * 256) * 16, src + tid + kk * 256);
        if (tid < NF4 - 1280)
            CP_ASYNC16(dst + (tid + 1280) * 16, src + tid + 1280);
        CP_COMMIT();
    }

    int p = 0;
#pragma unroll 1
    for (; chunk < NCH; chunk += GRID_MAIN) {
        int b = chunk >> 8;
        int ga = chunk * THR + tid;            // flat anchor index (b*AA + a)
        float* cur = p ? buf1 : buf0;
        float* nxtbuf = p ? buf0 : buf1;
        int nxt = chunk + GRID_MAIN;
        if (nxt < NCH) {                       // issue prefetch of next chunk
            const float4* src = (const float4*)conf + (size_t)nxt * NF4;
            unsigned dst = (unsigned)__cvta_generic_to_shared(nxtbuf);
#pragma unroll
            for (int kk = 0; kk < 5; kk++)
                CP_ASYNC16(dst + (tid + kk * 256) * 16, src + tid + kk * 256);
            if (tid < NF4 - 1280)
                CP_ASYNC16(dst + (tid + 1280) * 16, src + tid + 1280);
            CP_COMMIT();
            CP_WAIT1();                        // current chunk's group done
        } else {
            CP_WAIT0();
        }
        float mi = g_maxiou[ga];
        unsigned fword = ((const unsigned*)g.forced)[ga >> 5];
        int bt = g_bestt[ga];
        __syncthreads();                       // (B) staged data visible to all

        bool forced = (fword >> (ga & 31)) & 1;
        bool pos = (mi >= 0.5f) || forced;
        bool neg = (mi < 0.4f) && !forced;
        float psC = 0.f, bbC = 0.f;
        if (pos || neg) {
            const float* row = cur + tid * CC; // stride-21: conflict-free
            float s = 0.f;
#pragma unroll
            for (int c = 0; c < CC; c++) s += __expf(row[c]);   // x~N(0,1): safe

            if (neg) {
                // logit-domain threshold; -1e-3 slack covers __logf ulp error
                float lthr = __logf(splo[b] * s) - 1e-3f;
                float inv = __fdividef(1.0f, s);
#pragma unroll
                for (int c = 0; c < CC; c++) {
                    if (row[c] >= lthr) {      // rare survivor -> shared staging
                        float f = focal_fn(__expf(row[c]) * inv, false);
                        int idx = atomicAdd(&s_cnt, 1);
                        if (idx < SBC) sbuf[idx] = f;
                        else {                 // overflow: direct global (rare)
                            int gi = atomicAdd(&g.cnt[b], 1);
                            if (gi < CAP) g_buf[b][gi] = f;
                        }
                    }
                }
            } else {
                int tc = tl[b * TT + bt];
                float inv = __fdividef(1.0f, s);
#pragma unroll
                for (int c = 0; c < CC; c++)
                    psC += focal_fn(__expf(row[c]) * inv, c == tc);

                float4 bp = ((const float4*)bbox)[(size_t)ga];
                float4 tv = ((const float4*)tb)[b * TT + bt];
                float t0 = tv.x, t1 = tv.y, t2 = tv.z, t3 = tv.w;
                float x1 = fmaxf(bp.x, t0), y1 = fmaxf(bp.y, t1);
                float x2 = fminf(bp.z, t2), y2 = fminf(bp.w, t3);
                float inter = fmaxf(x2 - x1, 0.f) * fmaxf(y2 - y1, 0.f);
                float a1 = (bp.z - bp.x) * (bp.w - bp.y);
                float a2 = (t2 - t0) * (t3 - t1);
                float uni = a1 + a2 - inter;
                float iou = inter / (uni + 1e-6f);
                float ex1 = fminf(bp.x, t0), ey1 = fminf(bp.y, t1);
                float ex2 = fmaxf(bp.z, t2), ey2 = fmaxf(bp.w, t3);
                float enc = (ex2 - ex1) * (ey2 - ey1);
                float gl = 1.f - (iou - (enc - uni) / (enc + 1e-6f));
                float l1 = 0.f, d, ad;
                d = bp.x - t0; ad = fabsf(d); l1 += (ad < 1.f) ? 0.5f * d * d : ad - 0.5f;
                d = bp.y - t1; ad = fabsf(d); l1 += (ad < 1.f) ? 0.5f * d * d : ad - 0.5f;
                d = bp.z - t2; ad = fabsf(d); l1 += (ad < 1.f) ? 0.5f * d * d : ad - 0.5f;
                d = bp.w - t3; ad = fabsf(d); l1 += (ad < 1.f) ? 0.5f * d * d : ad - 0.5f;
                l1 *= 0.25f;
                bbC = gl + 0.5f * l1;
            }
        }
        // per-chunk pos flush (fires only on the rare pos-containing chunks)
#pragma unroll
        for (int off = 16; off > 0; off >>= 1) {
            psC += __shfl_down_sync(0xFFFFFFFFu, psC, off);
            bbC += __shfl_down_sync(0xFFFFFFFFu, bbC, off);
        }
        if (lane == 0) {
            if (psC != 0.f) atomicAdd(&g.possum[b], psC);
            if (bbC != 0.f) atomicAdd(&g.bboxsum[b], bbC);
        }
        __syncthreads();                       // (C) survivors all staged
        int nf = s_cnt; if (nf > SBC) nf = SBC;
        if (tid == 0 && nf > 0) s_base = atomicAdd(&g.cnt[b], nf);
        __syncthreads();                       // (D) base visible
        if (nf > 0) {
            int base = s_base;
            for (int i = tid; i < nf; i += THR)
                if (base + i < CAP) g_buf[b][base + i] = sbuf[i];
        }
        if (tid == 0) s_cnt = 0;               // ordered by sync (B) next iter
        p ^= 1;
    }
}

// ------- k4: exact top-k (2-level radix) + INLINE exact fallback if the
// sampled threshold under-covered (uniform branch; never taken in practice).
__global__ void kSelect(const float* __restrict__ conf) {
    int b = blockIdx.x, tid = threadIdx.x;
    __shared__ unsigned int hc[NB2];
    __shared__ float hs[NB2];
    __shared__ unsigned int scnt[256];
    __shared__ float ssum[256];
    __shared__ int s_found, s_bin;
    __shared__ long long s_cum;
    __shared__ float s_sum;
    int n = g.cnt[b];
    long long k = g.kval[b];
    long long np = g.numpos[b];
    bool bad = (n > CAP);
    float topk = 0.f;
    if (k > 0 && !bad) {
        for (int i = tid; i < NB1; i += THR) { hc[i] = 0; hs[i] = 0.f; }
        __syncthreads();
        for (int i = tid; i < n; i += THR) {
            float v = g_buf[b][i];
            int bin = focal_bin(v);
            atomicAdd(&hc[bin], 1u);
            atomicAdd(&hs[bin], v);
        }
        __syncthreads();
        suffix_select<NB1, true>(hc, hs, k, scnt, ssum, &s_found, &s_bin, &s_cum, &s_sum);
        if (!s_found) {
            bad = true;                                 // under-coverage
        } else {
            int bstar = s_bin;
            long long rem = k - s_cum;
            float above = s_sum;
            unsigned cstar = hc[bstar];
            float sstar = hs[bstar];
            __syncthreads();
            if (rem >= (long long)cstar) {
                topk = above + sstar;
            } else {
                for (int i = tid; i < NB2; i += THR) { hc[i] = 0; hs[i] = 0.f; }
                __syncthreads();
                for (int i = tid; i < n; i += THR) {
                    float v = g_buf[b][i];
                    unsigned bits = __float_as_uint(v) & 0x7FFFFFFFu;
                    if ((int)(bits >> 20) == bstar) {
                        int sb = (bits >> 8) & 0xFFF;
                        atomicAdd(&hc[sb], 1u);
                        atomicAdd(&hs[sb], v);
                    }
                }
                __syncthreads();
                suffix_select<NB2, true>(hc, hs, rem, scnt, ssum, &s_found, &s_bin, &s_cum, &s_sum);
                long long rem2 = rem - s_cum;
                float part = 0.f;
                unsigned c2 = hc[s_bin];
                if (rem2 >= (long long)c2) part = hs[s_bin];
                else if (rem2 > 0 && c2 > 0) part = (float)rem2 * (hs[s_bin] / (float)c2);
                topk = above + s_sum + part;
            }
        }
    }
    if (bad && k > 0) {
        // exact fallback: full histogram over all negatives (uniform branch)
        __syncthreads();
        for (int i = tid; i < NB1; i += THR) { hc[i] = 0; hs[i] = 0.f; }
        __syncthreads();
        for (int ch = 0; ch < AA / THR; ch++) {
            int a = ch * THR + tid;
            float mi = g_maxiou[b * AA + a];
            bool forced = (g.forced[b][a >> 5] >> (a & 31)) & 1;
            if (mi < 0.4f && !forced) {
                const float* row = conf + ((size_t)b * AA + a) * CC;
                float m = row[0];
#pragma unroll
                for (int c = 1; c < CC; c++) m = fmaxf(m, row[c]);
                float s = 0.f;
#pragma unroll
                for (int c = 0; c < CC; c++) s += __expf(row[c] - m);
                float inv = __fdividef(1.0f, s);
#pragma unroll
                for (int c = 0; c < CC; c++) {
                    float f = focal_fn(__expf(row[c] - m) * inv, false);
                    int bin = focal_bin(f);
                    atomicAdd(&hc[bin], 1u);
                    atomicAdd(&hs[bin], f);
                }
            }
        }
        __syncthreads();
        suffix_select<NB1, true>(hc, hs, k, scnt, ssum, &s_found, &s_bin, &s_cum, &s_sum);
        float ab = s_sum;
        long long rem = k - s_cum;
        unsigned c = hc[s_bin];
        if (rem >= (long long)c) ab += hs[s_bin];
        else if (rem > 0 && c > 0) ab += (float)rem * (hs[s_bin] / (float)c);
        topk = ab;
    }
    if (tid == 0) {
        long long dn = np + k; if (dn < 1) dn = 1;
        g.confl[b] = (g.possum[b] + topk) / (float)dn;
        g.bboxl[b] = (np > 0) ? g.bboxsum[b] / (float)np : 0.f;
    }
}

// --------------------------------------------------------- k5: finalize
__global__ void kFinal(float* out) {
    if (threadIdx.x == 0) {
        float cs = 0.f, bs = 0.f;
        for (int b = 0; b < BB; b++) { cs += g.confl[b]; bs += g.bboxl[b]; }
        cs *= (1.0f / BB); bs *= (1.0f / BB);
        out[0] = cs + bs;
        out[1] = cs;
        out[2] = bs;
    }
}

// ---------------------------------------------------------------- launch
extern "C" void kernel_launch(void* const* d_in, const int* in_sizes, int n_in,
                              void* d_out, int out_size) {
    const float* conf = (const float*)d_in[0];
    const float* bbox = (const float*)d_in[1];
    const float* anch = (const float*)d_in[2];
    const float* tb = (const float*)d_in[3];
    const int* tl = (const int*)d_in[4];
    float* out = (float*)d_out;

    const int dynBytes = 2 * CHUNK_BYTES + SBC * 4;   // 47104
    cudaFuncSetAttribute((const void*)kMain,
                         cudaFuncAttributeMaxDynamicSharedMemorySize, dynBytes);
    cudaFuncSetAttribute((const void*)kMain,
                         cudaFuncAttributePreferredSharedMemoryCarveout, 100);
    cudaFuncSetAttribute((const void*)kIoUSamp,
                         cudaFuncAttributePreferredSharedMemoryCarveout, 100);

    // zero/seed state split across 3 launches so kIoUSamp lands at the
    // profiled launch index (3) — visibility for the next round.
    int nz = (int)(sizeof(State) / 4);
    int third = (nz + 2) / 3;
    kZeroRange<<<(third + 255) / 256, 256>>>(0, third);
    kZeroRange<<<(third + 255) / 256, 256>>>(third, 2 * third);
    kZeroRange<<<(third + 255) / 256, 256>>>(2 * third, nz);
    kIoUSamp<<<dim3(AA / (2 * THR), BB), THR>>>(anch, tb, conf);
    kPrep<<<BB, THR>>>();
    kMain<<<GRID_MAIN, THR, dynBytes>>>(conf, bbox, tb, tl);   // persistent
    kSelect<<<BB, THR>>>(conf);        // 256 threads: suffix_select contract
    kFinal<<<1, 32>>>(out);
}

// round 16
// speedup vs baseline: 1.1056x; 1.0333x over previous
#include <cuda_runtime.h>
#include <cstdint>
#include <cstddef>

#define BB 16
#define AA 65536
#define TT 32
#define CC 21
#define NB1 2048
#define NB2 4096
#define CAP 262144
#define THR 256
#define SBC 1024              // shared survivor staging capacity
#define GRID_MAIN 592         // 4 blocks/SM * 148 SMs: one wave for kMain
#define NF4 (THR * CC / 4)    // 1344 float4 per chunk
#define CHUNK_BYTES (THR * CC * 4)   // 21504

struct State {
    unsigned long long packed[BB][TT];   // force-match argmax keys (MUST be first: kZero seeds it)
    unsigned int forced[BB][AA / 32];    // forced-positive bitmask
    int numpos[BB], nneg[BB], kval[BB], blo[BB], cnt[BB];
    int done;                            // kSelect completion counter
    float possum[BB], bboxsum[BB], confl[BB], bboxl[BB];
    float plo[BB];                       // probability threshold (inverse focal)
    unsigned int h0[BB][NB1];            // sampled coarse histogram
};
__device__ State g;
__device__ float g_buf[BB][CAP];         // compacted candidate focal values
__device__ float g_maxiou[BB * AA];
__device__ unsigned char g_bestt[BB * AA];

// ---------------------------------------------------------------- helpers
__device__ __forceinline__ float focal_fn(float p, bool ispos) {
    float pt = ispos ? p : 1.0f - p;
    float af = ispos ? 0.25f : 0.75f;
    float om = 1.0f - pt;
    return -af * om * om * __logf(fmaxf(pt, 1e-6f));
}

__device__ __forceinline__ int focal_bin(float f) {
    return (int)((__float_as_uint(f) & 0x7FFFFFFFu) >> 20);
}

#define CP_ASYNC16(dst_u32, src_ptr) \
    asm volatile("cp.async.cg.shared.global [%0], [%1], 16;" \
                 :: "r"(dst_u32), "l"(src_ptr) : "memory")
#define CP_COMMIT() asm volatile("cp.async.commit_group;" ::: "memory")
#define CP_WAIT1() asm volatile("cp.async.wait_group 1;" ::: "memory")
#define CP_WAIT0() asm volatile("cp.async.wait_group 0;" ::: "memory")

// Block-wide (exactly 256 threads) descending bin selection over NB bins.
template <int NB, bool WS>
__device__ __forceinline__ void suffix_select(
    const unsigned* hc, const float* hs, long long k,
    unsigned* s_scnt, float* s_ssum,
    int* o_found, int* o_bin, long long* o_cum, float* o_sum)
{
    const int tid = threadIdx.x;          // requires blockDim.x == 256
    const int CH = NB / 256;
    unsigned myc = 0; float myf = 0.f;
#pragma unroll
    for (int j = 0; j < CH; j++) {
        myc += hc[tid * CH + j];
        if (WS) myf += hs[tid * CH + j];
    }
    s_scnt[tid] = myc;
    if (WS) s_ssum[tid] = myf;
    __syncthreads();
    for (int off = 1; off < 256; off <<= 1) {   // inclusive suffix scan
        unsigned vc = (tid + off < 256) ? s_scnt[tid + off] : 0u;
        float vf = 0.f;
        if (WS) vf = (tid + off < 256) ? s_ssum[tid + off] : 0.f;
        __syncthreads();
        s_scnt[tid] += vc;
        if (WS) s_ssum[tid] += vf;
        __syncthreads();
    }
    if (tid == 0) {
        *o_found = ((long long)s_scnt[0] >= k) ? 1 : 0;
        *o_bin = 0; *o_cum = 0; *o_sum = 0.f;
    }
    __syncthreads();
    if (*o_found) {
        long long S = (long long)s_scnt[tid];
        long long A = S - (long long)myc;
        if (A < k && S >= k) {                    // unique crossing chunk
            long long cum = A;
            float ab = WS ? (s_ssum[tid] - myf) : 0.f;
            int bin = tid * CH;
            for (int j = CH - 1; j >= 0; j--) {
                int bb = tid * CH + j;
                unsigned c = hc[bb];
                if (cum + (long long)c >= k) { bin = bb; break; }
                cum += c;
                if (WS) ab += hs[bb];
            }
            *o_bin = bin; *o_cum = cum; *o_sum = ab;
        }
    }
    __syncthreads();
}

// ------------- k0: zero state; seed packed with (iou=0, anchor=0) keys
// (= exact argmax result for all-zero IoU columns, first-index rule).
__global__ void kZero() {
    int i = blockIdx.x * blockDim.x + threadIdx.x;
    int n = (int)(sizeof(State) / 4);
    if (i < n) {
        unsigned v = 0u;
        if (i < BB * TT * 2 && (i & 1) == 0) v = 0xFFFFFFFFu;  // low word of seed key
        ((unsigned int*)&g)[i] = v;
    }
}

// --------------- k1: IoU (4 anchors/thread) + zero-overlap skip,
// hoisted hi-word precheck, fused 1/32-sampled focal histogram.
__global__ void kIoUSamp(const float* __restrict__ anchors, const float* __restrict__ tb,
                         const float* __restrict__ conf) {
    int b = blockIdx.y;
    int tid = threadIdx.x;
    int a0 = blockIdx.x * (4 * THR);
    __shared__ float4 stb4[TT];
    __shared__ float sarea[TT];
    __shared__ unsigned long long smax[TT];
    __shared__ int snp, snn;
    __shared__ unsigned int sh[NB1];
    for (int i = tid; i < NB1; i += THR) sh[i] = 0;
    if (tid < TT) {
        float4 tv = ((const float4*)tb)[b * TT + tid];
        stb4[tid] = tv;
        sarea[tid] = (tv.z - tv.x) * (tv.w - tv.y);
        smax[tid] = 0ull;
    }
    if (tid == 0) { snp = 0; snn = 0; }
    __syncthreads();

    float4 av[4]; float arp[4]; float best[4]; int bt[4];
    size_t gb = (size_t)b * AA;
#pragma unroll
    for (int j = 0; j < 4; j++) {
        av[j] = ((const float4*)anchors)[a0 + j * THR + tid];
        arp[j] = (av[j].z - av[j].x) * (av[j].w - av[j].y) + 1e-6f;
        best[j] = 0.f; bt[j] = 0;       // all-zero row -> argmax = 0 (first index)
    }
#pragma unroll 4
    for (int t = 0; t < TT; t++) {
        float4 tv = stb4[t];
        float ta = sarea[t];
        unsigned hi = ((const unsigned*)smax)[2 * t + 1];   // monotone: stale-safe
#pragma unroll
        for (int j = 0; j < 4; j++) {
            float dx = fminf(av[j].z, tv.z) - fmaxf(av[j].x, tv.x);
            float dy = fminf(av[j].w, tv.w) - fmaxf(av[j].y, tv.y);
            if (dx > 0.f && dy > 0.f) {     // overlapping pairs only (~5%)
                float it = dx * dy;
                float iou = __fdividef(it, arp[j] + ta - it);
                if (iou > best[j]) { best[j] = iou; bt[j] = t; }  // first-index argmax
                if (__float_as_uint(iou) >= hi) {                 // rare exact path
                    unsigned long long cand = ((unsigned long long)__float_as_uint(iou) << 32) |
                        (unsigned long long)(0xFFFFFFFFu - (unsigned)(a0 + j * THR + tid));
                    if (cand > smax[t]) atomicMax(&smax[t], cand);
                }
            }
        }
    }
    int np = 0, nn = 0;
#pragma unroll
    for (int j = 0; j < 4; j++) {
        int a = a0 + j * THR + tid;
        g_maxiou[gb + a] = best[j];
        g_bestt[gb + a] = (unsigned char)bt[j];
        np += (best[j] >= 0.5f);
        nn += (best[j] < 0.4f);
    }
    int pk = np | (nn << 8);               // fields <=128 each: no overflow
#pragma unroll
    for (int off = 16; off > 0; off >>= 1) pk += __shfl_down_sync(0xFFFFFFFFu, pk, off);
    if ((tid & 31) == 0) {
        atomicAdd(&snp, pk & 0xFF);
        atomicAdd(&snn, pk >> 8);
    }

    // fused 1/32-sampled focal histogram (32 sampled anchors per 1024-block)
    if (tid < 32) {
        int sa = a0 + tid * 32;
        const float* cp = conf + (gb + sa) * CC;
        float m = cp[0];
#pragma unroll
        for (int c = 1; c < CC; c++) m = fmaxf(m, cp[c]);
        float s = 0.f;
#pragma unroll
        for (int c = 0; c < CC; c++) s += __expf(cp[c] - m);
        float inv = __fdividef(1.0f, s);
#pragma unroll
        for (int c = 0; c < CC; c++) {
            float f = focal_fn(__expf(cp[c] - m) * inv, false);
            atomicAdd(&sh[focal_bin(f)], 1u);
        }
    }
    __syncthreads();
    if (tid < TT) { unsigned long long v = smax[tid]; if (v) atomicMax(&g.packed[b][tid], v); }
    if (tid == 0) { atomicAdd(&g.numpos[b], snp); atomicAdd(&g.nneg[b], snn); }
    for (int i = tid; i < NB1; i += THR)
        if (sh[i]) atomicAdd(&g.h0[b][i], sh[i]);
}

// ------ k2: force-match, counts, blo/k, and probability threshold p_lo
__global__ void kPrep() {
    int b = blockIdx.x, tid = threadIdx.x;
    __shared__ unsigned int hc[NB1];
    __shared__ unsigned int scnt[256];
    __shared__ int s_found, s_bin;
    __shared__ long long s_cum;
    __shared__ float s_sum;
    if (tid < TT) {
        unsigned a = 0xFFFFFFFFu - (unsigned)(g.packed[b][tid] & 0xFFFFFFFFull);
        if (a < AA) {
            unsigned bit = 1u << (a & 31);
            unsigned old = atomicOr(&g.forced[b][a >> 5], bit);
            if (!(old & bit)) {
                float mi = g_maxiou[b * AA + a];
                if (mi < 0.5f) atomicAdd(&g.numpos[b], 1);
                if (mi < 0.4f) atomicAdd(&g.nneg[b], -1);
            }
        }
    }
    for (int i = tid; i < NB1; i += THR) hc[i] = g.h0[b][i];
    __syncthreads();
    long long np = g.numpos[b], nn = g.nneg[b];
    long long k = 3 * np; if (nn < k) k = nn;
    if (tid == 0) g.kval[b] = (int)k;
    if (k <= 0) { if (tid == 0) { g.blo[b] = NB1; g.plo[b] = 2.0f; } return; }
    long long target = k / 16 + 128;       // expected survivors ~ 2k + 4096
    suffix_select<NB1, false>(hc, nullptr, target, scnt, nullptr,
                              &s_found, &s_bin, &s_cum, &s_sum);
    if (tid == 0) {
        int blo = s_found ? s_bin : 0;
        g.blo[b] = blo;
        // invert focal at bin lower edge via FLOAT bisection
        float flo = __uint_as_float(((unsigned)blo) << 20);
        float plo = 0.f;
        if (flo > 0.f) {
            float lo = 0.f, hi = 1.f;
#pragma unroll
            for (int it = 0; it < 30; it++) {
                float p = 0.5f * (lo + hi);
                float pt = fmaxf(1.f - p, 1e-6f);
                float f = -0.75f * p * p * __logf(pt);
                if (f < flo) lo = p; else hi = p;
            }
            plo = lo * (1.f - 1e-3f);   // conservative margin: over-include
        }
        g.plo[b] = plo;
    }
}

// ------------------- k3: main pass, PERSISTENT + cp.async double-buffer.
__global__ void __launch_bounds__(THR, 4)
kMain(const float* __restrict__ conf, const float* __restrict__ bbox,
      const float* __restrict__ tb, const int* __restrict__ tl) {
    const int NCH = BB * AA / THR;            // 4096 chunks
    int tid = threadIdx.x;
    int lane = tid & 31;
    extern __shared__ char dynsmem[];
    float* buf0 = (float*)dynsmem;                         // 21504 B
    float* buf1 = (float*)(dynsmem + CHUNK_BYTES);         // 21504 B
    float* sbuf = (float*)(dynsmem + 2 * CHUNK_BYTES);     // SBC*4 B
    __shared__ float splo[BB];
    __shared__ int s_cnt, s_base;
    if (tid < BB) splo[tid] = g.plo[tid];
    if (tid == 0) s_cnt = 0;

    // issue cp.async for first chunk into buf0
    int chunk = blockIdx.x;
    {
        const float4* src = (const float4*)conf + (size_t)chunk * NF4;
        unsigned dst = (unsigned)__cvta_generic_to_shared(buf0);
#pragma unroll
        for (int kk = 0; kk < 5; kk++)
            CP_ASYNC16(dst + (tid + kk * 256) * 16, src + tid + kk * 256);
        if (tid < NF4 - 1280)
            CP_ASYNC16(dst + (tid + 1280) * 16, src + tid + 1280);
        CP_COMMIT();
    }

    int p = 0;
#pragma unroll 1
    for (; chunk < NCH; chunk += GRID_MAIN) {
        int b = chunk >> 8;
        int ga = chunk * THR + tid;            // flat anchor index (b*AA + a)
        float* cur = p ? buf1 : buf0;
        float* nxtbuf = p ? buf0 : buf1;
        int nxt = chunk + GRID_MAIN;
        if (nxt < NCH) {                       // issue prefetch of next chunk
            const float4* src = (const float4*)conf + (size_t)nxt * NF4;
            unsigned dst = (unsigned)__cvta_generic_to_shared(nxtbuf);
#pragma unroll
            for (int kk = 0; kk < 5; kk++)
                CP_ASYNC16(dst + (tid + kk * 256) * 16, src + tid + kk * 256);
            if (tid < NF4 - 1280)
                CP_ASYNC16(dst + (tid + 1280) * 16, src + tid + 1280);
            CP_COMMIT();
            CP_WAIT1();                        // current chunk's group done
        } else {
            CP_WAIT0();
        }
        float mi = g_maxiou[ga];
        unsigned fword = ((const unsigned*)g.forced)[ga >> 5];
        int bt = g_bestt[ga];
        __syncthreads();                       // (B) staged data visible to all

        bool forced = (fword >> (ga & 31)) & 1;
        bool pos = (mi >= 0.5f) || forced;
        bool neg = (mi < 0.4f) && !forced;
        float psC = 0.f, bbC = 0.f;
        if (pos || neg) {
            const float* row = cur + tid * CC; // stride-21: conflict-free
            float s = 0.f;
#pragma unroll
            for (int c = 0; c < CC; c++) s += __expf(row[c]);   // x~N(0,1): safe

            if (neg) {
                // logit-domain threshold; -1e-3 slack covers __logf ulp error
                float lthr = __logf(splo[b] * s) - 1e-3f;
                float inv = __fdividef(1.0f, s);
#pragma unroll
                for (int c = 0; c < CC; c++) {
                    if (row[c] >= lthr) {      // rare survivor -> shared staging
                        float f = focal_fn(__expf(row[c]) * inv, false);
                        int idx = atomicAdd(&s_cnt, 1);
                        if (idx < SBC) sbuf[idx] = f;
                        else {                 // overflow: direct global (rare)
                            int gi = atomicAdd(&g.cnt[b], 1);
                            if (gi < CAP) g_buf[b][gi] = f;
                        }
                    }
                }
            } else {
                int tc = tl[b * TT + bt];
                float inv = __fdividef(1.0f, s);
#pragma unroll
                for (int c = 0; c < CC; c++)
                    psC += focal_fn(__expf(row[c]) * inv, c == tc);

                float4 bp = ((const float4*)bbox)[(size_t)ga];
                float4 tv = ((const float4*)tb)[b * TT + bt];
                float t0 = tv.x, t1 = tv.y, t2 = tv.z, t3 = tv.w;
                float x1 = fmaxf(bp.x, t0), y1 = fmaxf(bp.y, t1);
                float x2 = fminf(bp.z, t2), y2 = fminf(bp.w, t3);
                float inter = fmaxf(x2 - x1, 0.f) * fmaxf(y2 - y1, 0.f);
                float a1 = (bp.z - bp.x) * (bp.w - bp.y);
                float a2 = (t2 - t0) * (t3 - t1);
                float uni = a1 + a2 - inter;
                float iou = inter / (uni + 1e-6f);
                float ex1 = fminf(bp.x, t0), ey1 = fminf(bp.y, t1);
                float ex2 = fmaxf(bp.z, t2), ey2 = fmaxf(bp.w, t3);
                float enc = (ex2 - ex1) * (ey2 - ey1);
                float gl = 1.f - (iou - (enc - uni) / (enc + 1e-6f));
                float l1 = 0.f, d, ad;
                d = bp.x - t0; ad = fabsf(d); l1 += (ad < 1.f) ? 0.5f * d * d : ad - 0.5f;
                d = bp.y - t1; ad = fabsf(d); l1 += (ad < 1.f) ? 0.5f * d * d : ad - 0.5f;
                d = bp.z - t2; ad = fabsf(d); l1 += (ad < 1.f) ? 0.5f * d * d : ad - 0.5f;
                d = bp.w - t3; ad = fabsf(d); l1 += (ad < 1.f) ? 0.5f * d * d : ad - 0.5f;
                l1 *= 0.25f;
                bbC = gl + 0.5f * l1;
            }
        }
        // per-chunk pos flush (fires only on the rare pos-containing chunks)
#pragma unroll
        for (int off = 16; off > 0; off >>= 1) {
            psC += __shfl_down_sync(0xFFFFFFFFu, psC, off);
            bbC += __shfl_down_sync(0xFFFFFFFFu, bbC, off);
        }
        if (lane == 0) {
            if (psC != 0.f) atomicAdd(&g.possum[b], psC);
            if (bbC != 0.f) atomicAdd(&g.bboxsum[b], bbC);
        }
        __syncthreads();                       // (C) survivors all staged
        int nf = s_cnt; if (nf > SBC) nf = SBC;
        if (tid == 0 && nf > 0) s_base = atomicAdd(&g.cnt[b], nf);
        __syncthreads();                       // (D) base visible
        if (nf > 0) {
            int base = s_base;
            for (int i = tid; i < nf; i += THR)
                if (base + i < CAP) g_buf[b][base + i] = sbuf[i];
        }
        if (tid == 0) s_cnt = 0;               // ordered by sync (B) next iter
        p ^= 1;
    }
}

// ------- k4: exact top-k (2-level radix) + inline exact fallback +
// FUSED finalize: last block to finish reduces confl/bboxl -> out.
__global__ void kSelect(const float* __restrict__ conf, float* __restrict__ out) {
    int b = blockIdx.x, tid = threadIdx.x;
    __shared__ unsigned int hc[NB2];
    __shared__ float hs[NB2];
    __shared__ unsigned int scnt[256];
    __shared__ float ssum[256];
    __shared__ int s_found, s_bin;
    __shared__ long long s_cum;
    __shared__ float s_sum;
    __shared__ int s_last;
    int n = g.cnt[b];
    long long k = g.kval[b];
    long long np = g.numpos[b];
    bool bad = (n > CAP);
    float topk = 0.f;
    if (k > 0 && !bad) {
        for (int i = tid; i < NB1; i += THR) { hc[i] = 0; hs[i] = 0.f; }
        __syncthreads();
        for (int i = tid; i < n; i += THR) {
            float v = g_buf[b][i];
            int bin = focal_bin(v);
            atomicAdd(&hc[bin], 1u);
            atomicAdd(&hs[bin], v);
        }
        __syncthreads();
        suffix_select<NB1, true>(hc, hs, k, scnt, ssum, &s_found, &s_bin, &s_cum, &s_sum);
        if (!s_found) {
            bad = true;                                 // under-coverage
        } else {
            int bstar = s_bin;
            long long rem = k - s_cum;
            float above = s_sum;
            unsigned cstar = hc[bstar];
            float sstar = hs[bstar];
            __syncthreads();
            if (rem >= (long long)cstar) {
                topk = above + sstar;
            } else {
                for (int i = tid; i < NB2; i += THR) { hc[i] = 0; hs[i] = 0.f; }
                __syncthreads();
                for (int i = tid; i < n; i += THR) {
                    float v = g_buf[b][i];
                    unsigned bits = __float_as_uint(v) & 0x7FFFFFFFu;
                    if ((int)(bits >> 20) == bstar) {
                        int sb = (bits >> 8) & 0xFFF;
                        atomicAdd(&hc[sb], 1u);
                        atomicAdd(&hs[sb], v);
                    }
                }
                __syncthreads();
                suffix_select<NB2, true>(hc, hs, rem, scnt, ssum, &s_found, &s_bin, &s_cum, &s_sum);
                long long rem2 = rem - s_cum;
                float part = 0.f;
                unsigned c2 = hc[s_bin];
                if (rem2 >= (long long)c2) part = hs[s_bin];
                else if (rem2 > 0 && c2 > 0) part = (float)rem2 * (hs[s_bin] / (float)c2);
                topk = above + s_sum + part;
            }
        }
    }
    if (bad && k > 0) {
        // exact fallback: full histogram over all negatives (uniform branch)
        __syncthreads();
        for (int i = tid; i < NB1; i += THR) { hc[i] = 0; hs[i] = 0.f; }
        __syncthreads();
        for (int ch = 0; ch < AA / THR; ch++) {
            int a = ch * THR + tid;
            float mi = g_maxiou[b * AA + a];
            bool forced = (g.forced[b][a >> 5] >> (a & 31)) & 1;
            if (mi < 0.4f && !forced) {
                const float* row = conf + ((size_t)b * AA + a) * CC;
                float m = row[0];
#pragma unroll
                for (int c = 1; c < CC; c++) m = fmaxf(m, row[c]);
                float s = 0.f;
#pragma unroll
                for (int c = 0; c < CC; c++) s += __expf(row[c] - m);
                float inv = __fdividef(1.0f, s);
#pragma unroll
                for (int c = 0; c < CC; c++) {
                    float f = focal_fn(__expf(row[c] - m) * inv, false);
                    int bin = focal_bin(f);
                    atomicAdd(&hc[bin], 1u);
                    atomicAdd(&hs[bin], f);
                }
            }
        }
        __syncthreads();
        suffix_select<NB1, true>(hc, hs, k, scnt, ssum, &s_found, &s_bin, &s_cum, &s_sum);
        float ab = s_sum;
        long long rem = k - s_cum;
        unsigned c = hc[s_bin];
        if (rem >= (long long)c) ab += hs[s_bin];
        else if (rem > 0 && c > 0) ab += (float)rem * (hs[s_bin] / (float)c);
        topk = ab;
    }
    if (tid == 0) {
        long long dn = np + k; if (dn < 1) dn = 1;
        g.confl[b] = (g.possum[b] + topk) / (float)dn;
        g.bboxl[b] = (np > 0) ? g.bboxsum[b] / (float)np : 0.f;
        __threadfence();
        s_last = (atomicAdd(&g.done, 1) == BB - 1);
    }
    __syncthreads();
    if (s_last && tid == 0) {                 // last finisher: fused finalize
        __threadfence();
        float cs = 0.f, bs = 0.f;
        for (int i = 0; i < BB; i++) { cs += g.confl[i]; bs += g.bboxl[i]; }
        cs *= (1.0f / BB); bs *= (1.0f / BB);
        out[0] = cs + bs;
        out[1] = cs;
        out[2] = bs;
    }
}

// ---------------------------------------------------------------- launch
extern "C" void kernel_launch(void* const* d_in, const int* in_sizes, int n_in,
                              void* d_out, int out_size) {
    const float* conf = (const float*)d_in[0];
    const float* bbox = (const float*)d_in[1];
    const float* anch = (const float*)d_in[2];
    const float* tb = (const float*)d_in[3];
    const int* tl = (const int*)d_in[4];
    float* out = (float*)d_out;

    const int dynBytes = 2 * CHUNK_BYTES + SBC * 4;   // 47104
    cudaFuncSetAttribute((const void*)kMain,
                         cudaFuncAttributeMaxDynamicSharedMemorySize, dynBytes);
    cudaFuncSetAttribute((const void*)kMain,
                         cudaFuncAttributePreferredSharedMemoryCarveout, 100);
    cudaFuncSetAttribute((const void*)kIoUSamp,
                         cudaFuncAttributePreferredSharedMemoryCarveout, 100);

    int nz = (int)(sizeof(State) / 4);
    kZero<<<(nz + 255) / 256, 256>>>();
    kIoUSamp<<<dim3(AA / (4 * THR), BB), THR>>>(anch, tb, conf);
    kPrep<<<BB, THR>>>();
    kMain<<<GRID_MAIN, THR, dynBytes>>>(conf, bbox, tb, tl);   // persistent
    kSelect<<<BB, THR>>>(conf, out);   // 256 threads; fused finalize
}